// round 1
// baseline (speedup 1.0000x reference)
#include <cuda_runtime.h>
#include <math_constants.h>

// Until operator: out[b,t] = tau * lse_k( min(s2[t+k], -tau*lse_{j<=k}(-s1[t+j]/tau)) / tau )
// over k = 0..127 (a=0, b=127), tau = 0.01.
//
// All math done in base-2 log domain with inputs pre-scaled by C = (1/tau)*log2(e),
// so every transcendental is a single MUFU ex2/lg2.
//
// Padding: positions >= T get -1e30 in both tiles. For s1 this makes the A-update
// contribution ex2(-huge)=0 (matches reference PAD_BIG). For s2 it makes
// cand=-1e30 -> contribution ex2(-huge)=0 (matches the `valid` mask -inf fill).

#define TILE   512
#define WSTEPS 128

__device__ __forceinline__ float ex2f(float x) {
    float r; asm("ex2.approx.f32 %0, %1;" : "=f"(r) : "f"(x)); return r;
}
__device__ __forceinline__ float lg2f(float x) {
    float r; asm("lg2.approx.f32 %0, %1;" : "=f"(r) : "f"(x)); return r;
}

__global__ __launch_bounds__(TILE)
void until_kernel(const float* __restrict__ g1,
                  const float* __restrict__ g2,
                  float* __restrict__ out, int T) {
    __shared__ float sh1[TILE + WSTEPS];
    __shared__ float sh2[TILE + WSTEPS];

    const float C = 144.26950408889634f;  // (1/tau) * log2(e), tau = 0.01

    const int row = blockIdx.y;
    const int t0  = blockIdx.x * TILE;
    const float* r1 = g1 + (size_t)row * T;
    const float* r2 = g2 + (size_t)row * T;

    // Load + pre-scale tile (stage s1 as -C*s1 so the hot loop has zero FMULs).
    for (int i = threadIdx.x; i < TILE + WSTEPS; i += TILE) {
        int g = t0 + i;
        float v1, v2;
        if (g < T) {
            v1 = -C * __ldg(r1 + g);
            v2 =  C * __ldg(r2 + g);
        } else {
            v1 = -1e30f;   // no contribution to A (exp -> 0)
            v2 = -1e30f;   // cand -> -1e30, no contribution to M
        }
        sh1[i] = v1;
        sh2[i] = v2;
    }
    __syncthreads();

    const int i = threadIdx.x;

    // Online logsumexp state (base-2): A for smooth-min over s1, M for smooth-max.
    float am = -CUDART_INF_F, as = 0.0f;
    float mm = -CUDART_INF_F, ms = 0.0f;

#pragma unroll 8
    for (int k = 0; k < WSTEPS; ++k) {
        float x = sh1[i + k];            // -C * s1[t+k]
        float y = sh2[i + k];            //  C * s2[t+k]

        // A <- logaddexp2(A, x)   (online: max anchor + scaled sum)
        float d = x - am;
        float e = ex2f(-fabsf(d));
        as = (d > 0.0f) ? fmaf(as, e, 1.0f) : (as + e);
        am = fmaxf(am, x);

        // cand (scaled by C): min(C*s2, C*smoothmin) = min(y, -(am + log2(as)))
        float cand = fminf(y, -(am + lg2f(as)));

        // M <- logaddexp2(M, cand)
        float d2 = cand - mm;
        float e2 = ex2f(-fabsf(d2));
        ms = (d2 > 0.0f) ? fmaf(ms, e2, 1.0f) : (ms + e2);
        mm = fmaxf(mm, cand);
    }

    // out = tau * M_natural = (mm + log2(ms)) / C = (mm + log2(ms)) * tau*ln(2)
    out[(size_t)row * T + t0 + i] = (mm + lg2f(ms)) * 0.006931471805599453f;
}

extern "C" void kernel_launch(void* const* d_in, const int* in_sizes, int n_in,
                              void* d_out, int out_size) {
    const float* s1 = (const float*)d_in[0];
    const float* s2 = (const float*)d_in[1];
    float* out = (float*)d_out;

    const int T = 16384;
    const int B = out_size / T;   // 512

    dim3 grid(T / TILE, B);       // (32, 512)
    until_kernel<<<grid, TILE>>>(s1, s2, out, T);
}

// round 2
// speedup vs baseline: 1.3210x; 1.3210x over previous
#include <cuda_runtime.h>
#include <math_constants.h>

// Until operator: out[b,t] = tau * lse_k( min(s2[t+k], -tau*lse_{j<=k}(-s1[t+j]/tau)) / tau )
// over k = 0..127 (a=0, b=127), tau = 0.01. Base-2 log domain, inputs pre-scaled
// by C = (1/tau)*log2(e) so every transcendental is a single MUFU ex2/lg2.
//
// Early exit (EXACT): q_k = -(am+log2(as)) is non-increasing; cand_k <= q_k; mm is
// non-decreasing and ms >= 1. Once q < mm - 30, all future e2 < 2^-30 and
// ms + e2 == ms in fp32, and mm can never change -> remaining steps are bitwise
// no-ops. Checked once per 8-step chunk with a warp vote.

#define TILE   512
#define WSTEPS 128
#define CHUNK  8

__device__ __forceinline__ float ex2f(float x) {
    float r; asm("ex2.approx.f32 %0, %1;" : "=f"(r) : "f"(x)); return r;
}
__device__ __forceinline__ float lg2f(float x) {
    float r; asm("lg2.approx.f32 %0, %1;" : "=f"(r) : "f"(x)); return r;
}

__global__ __launch_bounds__(TILE)
void until_kernel(const float* __restrict__ g1,
                  const float* __restrict__ g2,
                  float* __restrict__ out, int T) {
    __shared__ float2 sh[TILE + WSTEPS];   // {x = -C*s1, y = C*s2} interleaved -> 1 LDS.64/step

    const float C = 144.26950408889634f;  // (1/tau) * log2(e), tau = 0.01

    const int row = blockIdx.y;
    const int t0  = blockIdx.x * TILE;
    const float* r1 = g1 + (size_t)row * T;
    const float* r2 = g2 + (size_t)row * T;

    for (int i = threadIdx.x; i < TILE + WSTEPS; i += TILE) {
        int g = t0 + i;
        float2 v;
        if (g < T) {
            v.x = -C * __ldg(r1 + g);
            v.y =  C * __ldg(r2 + g);
        } else {
            v.x = -1e30f;   // no contribution to A (exp -> 0)
            v.y = -1e30f;   // cand -> -1e30, no contribution to M
        }
        sh[i] = v;
    }
    __syncthreads();

    const int i = threadIdx.x;

    // Online logsumexp state (base-2): A for smooth-min over s1, M for smooth-max.
    float am = -CUDART_INF_F, as = 0.0f;
    float mm = -CUDART_INF_F, ms = 0.0f;
    float qv = CUDART_INF_F;

    #pragma unroll 1
    for (int kb = 0; kb < WSTEPS; kb += CHUNK) {
        #pragma unroll
        for (int u = 0; u < CHUNK; ++u) {
            float2 v = sh[i + kb + u];
            float x = v.x;                   // -C * s1[t+k]
            float y = v.y;                   //  C * s2[t+k]

            // A <- logaddexp2(A, x)   (online: max anchor + scaled sum)
            float d = x - am;
            float e = ex2f(-fabsf(d));
            as = (d > 0.0f) ? fmaf(as, e, 1.0f) : (as + e);
            am = fmaxf(am, x);

            // q = C * smooth_min so far; cand = min(C*s2, q)
            qv = -(am + lg2f(as));
            float cand = fminf(y, qv);

            // M <- logaddexp2(M, cand)
            float d2 = cand - mm;
            float e2 = ex2f(-fabsf(d2));
            ms = (d2 > 0.0f) ? fmaf(ms, e2, 1.0f) : (ms + e2);
            mm = fmaxf(mm, cand);
        }
        // Exact early exit: all remaining updates are fp32 no-ops for every lane.
        if (__all_sync(0xffffffffu, qv < mm - 30.0f)) break;
    }

    // out = tau * M_natural = (mm + log2(ms)) * tau * ln(2)
    out[(size_t)row * T + t0 + i] = (mm + lg2f(ms)) * 0.006931471805599453f;
}

extern "C" void kernel_launch(void* const* d_in, const int* in_sizes, int n_in,
                              void* d_out, int out_size) {
    const float* s1 = (const float*)d_in[0];
    const float* s2 = (const float*)d_in[1];
    float* out = (float*)d_out;

    const int T = 16384;
    const int B = out_size / T;   // 512

    dim3 grid(T / TILE, B);       // (32, 512)
    until_kernel<<<grid, TILE>>>(s1, s2, out, T);
}